// round 14
// baseline (speedup 1.0000x reference)
#include <cuda_runtime.h>
#include <math.h>

#define B_  16
#define C_  512
#define HW_ 1024
#define C3_ 1536
#define NH_ 8
#define HC_ 64

static __device__ float g_norm[(size_t)2 * B_ * C_ * HW_];
static __device__ float g_t   [(size_t)2 * B_ * C3_ * HW_];
static __device__ float g_qkv [(size_t)2 * B_ * C3_ * HW_];
static __device__ float g_attn[(size_t)B_ * 2 * C_ * HW_];
static __device__ float g_stats[2 * B_ * 2];
static __device__ float g_part[2 * B_ * 16 * 2];
static __device__ float g_wcvt[2 * C3_ * C_ + 2 * C_ * C_];

// ---------------------------------------------------------------------------
// tf32 helpers
// ---------------------------------------------------------------------------
__device__ __forceinline__ unsigned f2tf32(float f) {
    unsigned r; asm("cvt.rna.tf32.f32 %0, %1;" : "=r"(r) : "f"(f)); return r;
}
__device__ __forceinline__ float tf32r(float f) {
    return __uint_as_float(f2tf32(f));
}
__device__ __forceinline__ void mma_tf32(float* c, const unsigned* a, const unsigned* b) {
    asm volatile(
        "mma.sync.aligned.m16n8k8.row.col.f32.tf32.tf32.f32 "
        "{%0,%1,%2,%3}, {%4,%5,%6,%7}, {%8,%9}, {%0,%1,%2,%3};"
        : "+f"(c[0]), "+f"(c[1]), "+f"(c[2]), "+f"(c[3])
        : "r"(a[0]), "r"(a[1]), "r"(a[2]), "r"(a[3]), "r"(b[0]), "r"(b[1]));
}
__device__ __forceinline__ void mma_u(float* c, unsigned a0, unsigned a1, unsigned a2,
                                      unsigned a3, unsigned b0, unsigned b1) {
    asm volatile(
        "mma.sync.aligned.m16n8k8.row.col.f32.tf32.tf32.f32 "
        "{%0,%1,%2,%3}, {%4,%5,%6,%7}, {%8,%9}, {%0,%1,%2,%3};"
        : "+f"(c[0]), "+f"(c[1]), "+f"(c[2]), "+f"(c[3])
        : "r"(a0), "r"(a1), "r"(a2), "r"(a3), "r"(b0), "r"(b1));
}

struct alignas(8) u2 { unsigned hi, lo; };

__device__ __forceinline__ u2 split_tf32(float x) {
    u2 r;
    asm("cvt.rna.tf32.f32 %0, %1;" : "=r"(r.hi) : "f"(x));
    float d = x - __uint_as_float(r.hi);
    asm("cvt.rna.tf32.f32 %0, %1;" : "=r"(r.lo) : "f"(d));
    return r;
}

__device__ __forceinline__ void cp16(void* sdst, const void* gsrc) {
    unsigned s = (unsigned)__cvta_generic_to_shared(sdst);
    asm volatile("cp.async.cg.shared.global [%0], [%1], 16;" :: "r"(s), "l"(gsrc));
}

// ---------------------------------------------------------------------------
// Kernel 0: pre-round GEMM weights to tf32 values
// ---------------------------------------------------------------------------
__global__ __launch_bounds__(256)
void cvt_weights(const float* __restrict__ wa, const float* __restrict__ wb,
                 const float* __restrict__ wp) {
    int idx = blockIdx.x * 256 + threadIdx.x;
    const int NA = C3_ * C_ / 4, NP = 2 * C_ * C_ / 4;
    float4 v;
    float4* dst = (float4*)g_wcvt;
    if (idx < NA)               v = ((const float4*)wa)[idx];
    else if (idx < 2 * NA)      v = ((const float4*)wb)[idx - NA];
    else if (idx < 2 * NA + NP) v = ((const float4*)wp)[idx - 2 * NA];
    else return;
    v.x = tf32r(v.x); v.y = tf32r(v.y); v.z = tf32r(v.z); v.w = tf32r(v.w);
    dst[idx] = v;
}

// ---------------------------------------------------------------------------
// Kernel 1a/1b: two-stage LayerNorm statistics
// ---------------------------------------------------------------------------
__global__ __launch_bounds__(256)
void ln_stats_part(const float* __restrict__ img, const float* __restrict__ wm) {
    int blk = blockIdx.x;
    int seg = blk & 15, sb = blk >> 4;
    int s = sb >> 4, b = sb & 15;
    const int SEG4 = C_ * HW_ / 4 / 16;
    const float4* x = (const float4*)((s ? wm : img) + (size_t)b * C_ * HW_)
                      + (size_t)seg * SEG4;
    float sum = 0.f, sq = 0.f;
    for (int i = threadIdx.x; i < SEG4; i += 256) {
        float4 v = x[i];
        sum += v.x + v.y + v.z + v.w;
        sq  += v.x * v.x + v.y * v.y + v.z * v.z + v.w * v.w;
    }
    __shared__ float s1[256], s2[256];
    s1[threadIdx.x] = sum; s2[threadIdx.x] = sq;
    __syncthreads();
    for (int st = 128; st > 0; st >>= 1) {
        if (threadIdx.x < st) {
            s1[threadIdx.x] += s1[threadIdx.x + st];
            s2[threadIdx.x] += s2[threadIdx.x + st];
        }
        __syncthreads();
    }
    if (threadIdx.x == 0) {
        g_part[blk * 2 + 0] = s1[0];
        g_part[blk * 2 + 1] = s2[0];
    }
}

__global__ void ln_stats_final() {
    int t = threadIdx.x;
    if (t >= 32) return;
    float sum = 0.f, sq = 0.f;
#pragma unroll
    for (int i = 0; i < 16; i++) {
        sum += g_part[(t * 16 + i) * 2 + 0];
        sq  += g_part[(t * 16 + i) * 2 + 1];
    }
    float inv_n = 1.f / (float)(C_ * HW_);
    float mu  = sum * inv_n;
    float var = sq * inv_n - mu * mu;
    g_stats[t * 2 + 0] = mu;
    g_stats[t * 2 + 1] = rsqrtf(var + 1e-5f);
}

// ---------------------------------------------------------------------------
// Kernel 2: apply LN affine, output tf32-rounded
// ---------------------------------------------------------------------------
__global__ __launch_bounds__(256)
void ln_apply(const float* __restrict__ img, const float* __restrict__ wm,
              const float* __restrict__ iw, const float* __restrict__ ib,
              const float* __restrict__ ww, const float* __restrict__ wb) {
    const int Q = C_ * HW_ / 4;
    size_t idx = (size_t)blockIdx.x * 256 + threadIdx.x;
    const size_t half = (size_t)B_ * Q;
    if (idx >= 2 * half) return;
    int s = idx >= half;
    size_t r = idx - (size_t)s * half;
    int b = (int)(r / Q);
    int chw = (int)(r % Q);
    const float4* x  = (const float4*)(s ? wm : img) + (size_t)b * Q;
    const float4* w  = (const float4*)(s ? ww : iw);
    const float4* bb = (const float4*)(s ? wb : ib);
    float mu   = g_stats[(s * 16 + b) * 2 + 0];
    float rstd = g_stats[(s * 16 + b) * 2 + 1];
    float4 xv = x[chw], wv = w[chw], bv = bb[chw];
    float4 o;
    o.x = tf32r((xv.x - mu) * rstd * wv.x + bv.x);
    o.y = tf32r((xv.y - mu) * rstd * wv.y + bv.y);
    o.z = tf32r((xv.z - mu) * rstd * wv.z + bv.z);
    o.w = tf32r((xv.w - mu) * rstd * wv.w + bv.w);
    ((float4*)g_norm)[idx] = o;
}

// ---------------------------------------------------------------------------
// Kernel 3/6: tf32 TC GEMM, kTile=32, cp.async double-buffered (dyn smem).
//   zHalf: blocks with blockIdx.z >= zHalf use A+strideA and bias2.
// Dynamic smem layout: As[2][4608] | Bs[2][4224]  (70656 bytes)
//   TA=false: As row stride 36 ([128][36]); TA=true: [32][132].
// ---------------------------------------------------------------------------
#define GT_AS 4608
#define GT_BS 4224
#define GT_SMEM ((2 * GT_AS + 2 * GT_BS) * 4)

template <bool TA>
__global__ __launch_bounds__(256)
void gemm_tc(const float* __restrict__ A, const float* __restrict__ Bm,
             float* __restrict__ Cm, const float* __restrict__ bias,
             const float* __restrict__ bias2, size_t strideA, int zHalf,
             int M, int N, int K, size_t strideB, size_t strideC) {
    extern __shared__ float dsm[];
    float* As = dsm;                    // [2][GT_AS]
    float* Bs = dsm + 2 * GT_AS;        // [2][GT_BS]
    if ((int)blockIdx.z >= zHalf) {
        A += strideA;
        bias = bias2;
    }
    const float* Bb = Bm + (size_t)blockIdx.z * strideB;
    float* Cb = Cm + (size_t)blockIdx.z * strideC;
    int m0 = blockIdx.y * 128, n0 = blockIdx.x * 128;
    int tid = threadIdx.x, lane = tid & 31, wid = tid >> 5;
    int warpM = wid & 3, warpN = wid >> 2;
    int gi = lane >> 2, li = lane & 3;

    float acc[2][8][4];
#pragma unroll
    for (int mi = 0; mi < 2; mi++)
#pragma unroll
        for (int ni = 0; ni < 8; ni++)
#pragma unroll
            for (int j = 0; j < 4; j++) acc[mi][ni][j] = 0.f;

    const int T = K / 32;

#define COPY_TILE(t, buf)                                                        \
    {                                                                            \
        int k0c = (t) * 32;                                                      \
        _Pragma("unroll")                                                        \
        for (int r = 0; r < 4; r++) {                                            \
            int idx = tid + r * 256;                                             \
            if (TA) {                                                            \
                int kl = idx >> 5, mq = idx & 31;                                \
                cp16(&As[(buf) * GT_AS + kl * 132 + mq * 4],                     \
                     &A[(size_t)(k0c + kl) * M + m0 + mq * 4]);                  \
            } else {                                                             \
                int ml = idx >> 3, kq = idx & 7;                                 \
                cp16(&As[(buf) * GT_AS + ml * 36 + kq * 4],                      \
                     &A[(size_t)(m0 + ml) * K + k0c + kq * 4]);                  \
            }                                                                    \
            int kl = idx >> 5, nq = idx & 31;                                    \
            cp16(&Bs[(buf) * GT_BS + kl * 132 + nq * 4],                         \
                 &Bb[(size_t)(k0c + kl) * N + n0 + nq * 4]);                     \
        }                                                                        \
        asm volatile("cp.async.commit_group;");                                  \
    }

    COPY_TILE(0, 0);

    for (int t = 0; t < T; t++) {
        int buf = t & 1;
        __syncthreads();
        if (t + 1 < T) {
            COPY_TILE(t + 1, buf ^ 1);
            asm volatile("cp.async.wait_group 1;");
        } else {
            asm volatile("cp.async.wait_group 0;");
        }
        __syncthreads();
#pragma unroll
        for (int ks = 0; ks < 4; ks++) {
            int k8 = ks * 8;
            unsigned ua[2][4];
#pragma unroll
            for (int mi = 0; mi < 2; mi++) {
                int m = warpM * 32 + mi * 16 + gi;
                if (TA) {
                    ua[mi][0] = __float_as_uint(As[buf * GT_AS + (k8 + li) * 132 + m]);
                    ua[mi][1] = __float_as_uint(As[buf * GT_AS + (k8 + li) * 132 + m + 8]);
                    ua[mi][2] = __float_as_uint(As[buf * GT_AS + (k8 + li + 4) * 132 + m]);
                    ua[mi][3] = __float_as_uint(As[buf * GT_AS + (k8 + li + 4) * 132 + m + 8]);
                } else {
                    ua[mi][0] = __float_as_uint(As[buf * GT_AS + m * 36 + k8 + li]);
                    ua[mi][1] = __float_as_uint(As[buf * GT_AS + (m + 8) * 36 + k8 + li]);
                    ua[mi][2] = __float_as_uint(As[buf * GT_AS + m * 36 + k8 + li + 4]);
                    ua[mi][3] = __float_as_uint(As[buf * GT_AS + (m + 8) * 36 + k8 + li + 4]);
                }
            }
            unsigned ub[8][2];
#pragma unroll
            for (int ni = 0; ni < 8; ni++) {
                int nn = warpN * 64 + ni * 8 + gi;
                ub[ni][0] = __float_as_uint(Bs[buf * GT_BS + (k8 + li) * 132 + nn]);
                ub[ni][1] = __float_as_uint(Bs[buf * GT_BS + (k8 + li + 4) * 132 + nn]);
            }
#pragma unroll
            for (int mi = 0; mi < 2; mi++)
#pragma unroll
                for (int ni = 0; ni < 8; ni++)
                    mma_tf32(acc[mi][ni], ua[mi], ub[ni]);
        }
    }

#pragma unroll
    for (int mi = 0; mi < 2; mi++) {
        int mrow = m0 + warpM * 32 + mi * 16 + gi;
        float bv0 = bias ? bias[mrow] : 0.f;
        float bv1 = bias ? bias[mrow + 8] : 0.f;
#pragma unroll
        for (int ni = 0; ni < 8; ni++) {
            int n = n0 + warpN * 64 + ni * 8 + 2 * li;
            float2 v0 = {acc[mi][ni][0] + bv0, acc[mi][ni][1] + bv0};
            float2 v1 = {acc[mi][ni][2] + bv1, acc[mi][ni][3] + bv1};
            *(float2*)&Cb[(size_t)mrow * N + n] = v0;
            *(float2*)&Cb[(size_t)(mrow + 8) * N + n] = v1;
        }
    }
}

// ---------------------------------------------------------------------------
// Kernel 4: grouped 3x3 conv, register-blocked
// ---------------------------------------------------------------------------
__global__ __launch_bounds__(256)
void dwconv_kernel(const float* __restrict__ wimg, const float* __restrict__ bimg,
                   const float* __restrict__ wwm,  const float* __restrict__ bwm) {
    __shared__ float sin_[6 * HW_];
    __shared__ float sw[162];
    __shared__ float sbias[6];
    int blk = blockIdx.x;
    int gp = blk & 255, sb = blk >> 8;
    int s = sb >> 4;
    int tid = threadIdx.x;
    int c0 = gp * 6;
    const float* in = g_t + ((size_t)sb * C3_ + c0) * HW_;
#pragma unroll
    for (int r = 0; r < 6; r++) {
        int idx = tid + r * 256;
        ((float4*)sin_)[idx] = ((const float4*)in)[idx];
    }
    const float* w = (s ? wwm : wimg) + (size_t)c0 * 27;
    if (tid < 162) sw[tid] = w[tid];
    if (tid < 6) sbias[tid] = (s ? bwm : bimg)[c0 + tid];
    __syncthreads();
    float* outp = g_qkv + ((size_t)sb * C3_ + c0) * HW_;
#pragma unroll
    for (int task = 0; task < 3; task++) {
        int t = task * 256 + tid;
        int o = t >> 7;
        int rest = t & 127;
        int y = rest >> 2;
        int seg = rest & 3;
        int x0 = seg * 8;
        float acc[8];
        float bv = sbias[o];
#pragma unroll
        for (int j = 0; j < 8; j++) acc[j] = bv;
        const float* wo = &sw[o * 27];
        const float* chan = &sin_[(o >= 3 ? 3 : 0) * HW_];
#pragma unroll
        for (int i = 0; i < 3; i++) {
            const float* cb = chan + i * HW_;
            const float* wi = wo + i * 9;
#pragma unroll
            for (int ky = 0; ky < 3; ky++) {
                int yy = y + ky - 1;
                if (yy < 0 || yy >= 32) continue;
                const float* rr = cb + yy * 32;
                float v[10];
                v[0] = (x0 > 0) ? rr[x0 - 1] : 0.f;
                float4 a4 = *(const float4*)&rr[x0];
                float4 b4 = *(const float4*)&rr[x0 + 4];
                v[1] = a4.x; v[2] = a4.y; v[3] = a4.z; v[4] = a4.w;
                v[5] = b4.x; v[6] = b4.y; v[7] = b4.z; v[8] = b4.w;
                v[9] = (x0 + 8 < 32) ? rr[x0 + 8] : 0.f;
                float w0 = wi[ky * 3 + 0], w1 = wi[ky * 3 + 1], w2 = wi[ky * 3 + 2];
#pragma unroll
                for (int j = 0; j < 8; j++)
                    acc[j] += w0 * v[j] + w1 * v[j + 1] + w2 * v[j + 2];
            }
        }
        float4 o0 = {acc[0], acc[1], acc[2], acc[3]};
        float4 o1 = {acc[4], acc[5], acc[6], acc[7]};
        *(float4*)&outp[(size_t)o * HW_ + y * 32 + x0] = o0;
        *(float4*)&outp[(size_t)o * HW_ + y * 32 + x0 + 4] = o1;
    }
}

// ---------------------------------------------------------------------------
// Kernel 5: TC cross-attention, tf32x3 (R11 version, best measured)
// ---------------------------------------------------------------------------
#define KS_STRIDE 35
#define QS_STRIDE 67
#define S_STRIDE  68
#define SMEM_KS_BYTES  (128 * KS_STRIDE * 8)
#define SMEM_QS_BYTES  (32 * QS_STRIDE * 8)
#define SMEM_S_OFF     (SMEM_KS_BYTES + SMEM_QS_BYTES)
#define SMEM_ATTN      (SMEM_S_OFF + 128 * S_STRIDE * 4)

__global__ __launch_bounds__(256)
void attn_tc_kernel() {
    extern __shared__ char smem_raw[];
    u2*    Ks = (u2*)smem_raw;
    u2*    Qs = (u2*)(smem_raw + SMEM_KS_BYTES);
    float* S  = (float*)(smem_raw + SMEM_S_OFF);

    int bid = blockIdx.x;
    int s = bid & 1, n = (bid >> 1) & 7, b = bid >> 4;
    int tid = threadIdx.x, lane = tid & 31, w = tid >> 5;
    int gi = lane >> 2, li = lane & 3;

    const size_t SB = (size_t)B_ * C3_ * HW_;
    const float* qbase  = g_qkv + (s ? SB : 0) + ((size_t)b * C3_ + n * HC_) * HW_;
    const float* k0base = g_qkv + ((size_t)b * C3_ + C_ + n * HC_) * HW_;
    const float* k1base = k0base + SB;
    const float* v0base = g_qkv + ((size_t)b * C3_ + 2 * C_ + n * HC_) * HW_;
    const float* v1base = v0base + SB;

    int r8 = tid >> 3;
    int q4 = (tid & 7) * 4;
    const float* kp[4];
    u2* kdst[4];
#pragma unroll
    for (int i = 0; i < 4; i++) {
        int kr = r8 + 32 * i;
        kp[i] = ((kr < 64) ? k0base + (size_t)kr * HW_
                           : k1base + (size_t)(kr - 64) * HW_) + q4;
        kdst[i] = &Ks[kr * KS_STRIDE + q4];
    }
    const float* qp[2];
#pragma unroll
    for (int i = 0; i < 2; i++)
        qp[i] = qbase + (size_t)(r8 + 32 * i) * HW_ + q4;
    const float* vp[4];
#pragma unroll
    for (int i = 0; i < 4; i++) {
        int kr = r8 + 32 * i;
        vp[i] = ((kr < 64) ? v0base + (size_t)kr * HW_
                           : v1base + (size_t)(kr - 64) * HW_) + q4;
    }

    int wM = w & 3, wN = w >> 2;
    float accS[2][4][4];
#pragma unroll
    for (int mi = 0; mi < 2; mi++)
#pragma unroll
        for (int ni = 0; ni < 4; ni++)
#pragma unroll
            for (int j = 0; j < 4; j++) accS[mi][ni][j] = 0.f;

    float4 kreg[4], qreg[2];
#pragma unroll
    for (int i = 0; i < 4; i++) kreg[i] = *(const float4*)kp[i];
#pragma unroll
    for (int i = 0; i < 2; i++) qreg[i] = *(const float4*)qp[i];

    for (int pc = 0; pc < 32; pc++) {
        __syncthreads();
#pragma unroll
        for (int i = 0; i < 4; i++) {
            kdst[i][0] = split_tf32(kreg[i].x); kdst[i][1] = split_tf32(kreg[i].y);
            kdst[i][2] = split_tf32(kreg[i].z); kdst[i][3] = split_tf32(kreg[i].w);
        }
#pragma unroll
        for (int i = 0; i < 2; i++) {
            int qr = r8 + 32 * i;
            Qs[(q4 + 0) * QS_STRIDE + qr] = split_tf32(qreg[i].x);
            Qs[(q4 + 1) * QS_STRIDE + qr] = split_tf32(qreg[i].y);
            Qs[(q4 + 2) * QS_STRIDE + qr] = split_tf32(qreg[i].z);
            Qs[(q4 + 3) * QS_STRIDE + qr] = split_tf32(qreg[i].w);
        }
        __syncthreads();
        if (pc < 31) {
            int off = (pc + 1) * 32;
#pragma unroll
            for (int i = 0; i < 4; i++) kreg[i] = *(const float4*)(kp[i] + off);
#pragma unroll
            for (int i = 0; i < 2; i++) qreg[i] = *(const float4*)(qp[i] + off);
        }
#pragma unroll
        for (int ks = 0; ks < 4; ks++) {
            int k8 = ks * 8;
            u2 a[2][4], bq[4][2];
#pragma unroll
            for (int mi = 0; mi < 2; mi++) {
                int m = wM * 32 + mi * 16 + gi;
                a[mi][0] = Ks[m * KS_STRIDE + k8 + li];
                a[mi][1] = Ks[(m + 8) * KS_STRIDE + k8 + li];
                a[mi][2] = Ks[m * KS_STRIDE + k8 + li + 4];
                a[mi][3] = Ks[(m + 8) * KS_STRIDE + k8 + li + 4];
            }
#pragma unroll
            for (int ni = 0; ni < 4; ni++) {
                int q = wN * 32 + ni * 8 + gi;
                bq[ni][0] = Qs[(k8 + li) * QS_STRIDE + q];
                bq[ni][1] = Qs[(k8 + li + 4) * QS_STRIDE + q];
            }
#pragma unroll
            for (int mi = 0; mi < 2; mi++)
#pragma unroll
                for (int ni = 0; ni < 4; ni++) {
                    float* c = accS[mi][ni];
                    mma_u(c, a[mi][0].hi, a[mi][1].hi, a[mi][2].hi, a[mi][3].hi,
                          bq[ni][0].hi, bq[ni][1].hi);
                    mma_u(c, a[mi][0].hi, a[mi][1].hi, a[mi][2].hi, a[mi][3].hi,
                          bq[ni][0].lo, bq[ni][1].lo);
                    mma_u(c, a[mi][0].lo, a[mi][1].lo, a[mi][2].lo, a[mi][3].lo,
                          bq[ni][0].hi, bq[ni][1].hi);
                }
        }
    }
#pragma unroll
    for (int mi = 0; mi < 2; mi++)
#pragma unroll
        for (int ni = 0; ni < 4; ni++) {
            int m = wM * 32 + mi * 16 + gi;
            int q = wN * 32 + ni * 8 + 2 * li;
            float2 v0 = {accS[mi][ni][0], accS[mi][ni][1]};
            float2 v1 = {accS[mi][ni][2], accS[mi][ni][3]};
            *(float2*)&S[m * S_STRIDE + q] = v0;
            *(float2*)&S[(m + 8) * S_STRIDE + q] = v1;
        }
    __syncthreads();

    if (tid < 128) {
        float* row = &S[tid * S_STRIDE];
        float mx = -1e30f;
#pragma unroll 8
        for (int j = 0; j < 64; j++) mx = fmaxf(mx, row[j]);
        float sum = 0.f;
#pragma unroll 8
        for (int j = 0; j < 64; j++) {
            float e = __expf(row[j] - mx);
            row[j] = e; sum += e;
        }
        float inv = 1.f / sum;
#pragma unroll 8
        for (int j = 0; j < 64; j++) row[j] *= inv;
    }

    int wM3 = w & 3, wN3 = w >> 2;
    float* outbase = g_attn + ((size_t)b * (2 * C_) + n * 128 + s * 64) * HW_;
    float4 vreg[4];
#pragma unroll
    for (int i = 0; i < 4; i++) vreg[i] = *(const float4*)vp[i];

    for (int pc = 0; pc < 32; pc++) {
        int p0 = pc * 32;
        __syncthreads();
#pragma unroll
        for (int i = 0; i < 4; i++) {
            kdst[i][0] = split_tf32(vreg[i].x); kdst[i][1] = split_tf32(vreg[i].y);
            kdst[i][2] = split_tf32(vreg[i].z); kdst[i][3] = split_tf32(vreg[i].w);
        }
        __syncthreads();
        if (pc < 31) {
            int off = (pc + 1) * 32;
#pragma unroll
            for (int i = 0; i < 4; i++) vreg[i] = *(const float4*)(vp[i] + off);
        }
        float acc3[2][4];
#pragma unroll
        for (int ni = 0; ni < 2; ni++)
#pragma unroll
            for (int j = 0; j < 4; j++) acc3[ni][j] = 0.f;
#pragma unroll
        for (int ks = 0; ks < 16; ks++) {
            int k8 = ks * 8;
            int m = wM3 * 16 + gi;
            u2 a0 = split_tf32(S[(k8 + li) * S_STRIDE + m]);
            u2 a1 = split_tf32(S[(k8 + li) * S_STRIDE + m + 8]);
            u2 a2 = split_tf32(S[(k8 + li + 4) * S_STRIDE + m]);
            u2 a3 = split_tf32(S[(k8 + li + 4) * S_STRIDE + m + 8]);
            u2 bv[2][2];
#pragma unroll
            for (int ni = 0; ni < 2; ni++) {
                int p = wN3 * 16 + ni * 8 + gi;
                bv[ni][0] = Ks[(k8 + li) * KS_STRIDE + p];
                bv[ni][1] = Ks[(k8 + li + 4) * KS_STRIDE + p];
            }
#pragma unroll
            for (int ni = 0; ni < 2; ni++) {
                float* c = acc3[ni];
                mma_u(c, a0.hi, a1.hi, a2.hi, a3.hi, bv[ni][0].hi, bv[ni][1].hi);
                mma_u(c, a0.hi, a1.hi, a2.hi, a3.hi, bv[ni][0].lo, bv[ni][1].lo);
                mma_u(c, a0.lo, a1.lo, a2.lo, a3.lo, bv[ni][0].hi, bv[ni][1].hi);
            }
        }
        int qrow = wM3 * 16 + gi;
#pragma unroll
        for (int ni = 0; ni < 2; ni++) {
            int p = p0 + wN3 * 16 + ni * 8 + 2 * li;
            float2 v0 = {tf32r(acc3[ni][0]), tf32r(acc3[ni][1])};
            float2 v1 = {tf32r(acc3[ni][2]), tf32r(acc3[ni][3])};
            *(float2*)&outbase[(size_t)qrow * HW_ + p] = v0;
            *(float2*)&outbase[(size_t)(qrow + 8) * HW_ + p] = v1;
        }
    }
}

// ---------------------------------------------------------------------------
extern "C" void kernel_launch(void* const* d_in, const int* in_sizes, int n_in,
                              void* d_out, int out_size) {
    const float* image     = (const float*)d_in[0];
    const float* watermark = (const float*)d_in[1];
    const float* img_ln_w  = (const float*)d_in[2];
    const float* img_ln_b  = (const float*)d_in[3];
    const float* wm_ln_w   = (const float*)d_in[4];
    const float* wm_ln_b   = (const float*)d_in[5];
    const float* img_pw_w  = (const float*)d_in[6];
    const float* img_pw_b  = (const float*)d_in[7];
    const float* img_dw_w  = (const float*)d_in[8];
    const float* img_dw_b  = (const float*)d_in[9];
    const float* wm_pw_w   = (const float*)d_in[10];
    const float* wm_pw_b   = (const float*)d_in[11];
    const float* wm_dw_w   = (const float*)d_in[12];
    const float* wm_dw_b   = (const float*)d_in[13];
    const float* proj      = (const float*)d_in[14];
    float* out = (float*)d_out;

    float *p_norm, *p_t, *p_attn, *p_wcvt;
    cudaGetSymbolAddress((void**)&p_norm, g_norm);
    cudaGetSymbolAddress((void**)&p_t,    g_t);
    cudaGetSymbolAddress((void**)&p_attn, g_attn);
    cudaGetSymbolAddress((void**)&p_wcvt, g_wcvt);

    cudaFuncSetAttribute(attn_tc_kernel,
                         cudaFuncAttributeMaxDynamicSharedMemorySize, SMEM_ATTN);
    cudaFuncSetAttribute(gemm_tc<false>,
                         cudaFuncAttributeMaxDynamicSharedMemorySize, GT_SMEM);
    cudaFuncSetAttribute(gemm_tc<true>,
                         cudaFuncAttributeMaxDynamicSharedMemorySize, GT_SMEM);

    // 0) pre-round GEMM weights
    int cvt4 = (2 * C3_ * C_ + 2 * C_ * C_) / 4;
    cvt_weights<<<(cvt4 + 255) / 256, 256>>>(img_pw_w, wm_pw_w, proj);

    // 1) LayerNorm (two-stage stats)
    ln_stats_part<<<512, 256>>>(image, watermark);
    ln_stats_final<<<1, 32>>>();
    size_t total4 = (size_t)2 * B_ * C_ * HW_ / 4;
    ln_apply<<<(unsigned)((total4 + 255) / 256), 256>>>(
        image, watermark, img_ln_w, img_ln_b, wm_ln_w, wm_ln_b);

    // 2) Pointwise 1x1 conv — both streams in one launch, kTile=32
    dim3 gpw(HW_ / 128, C3_ / 128, 2 * B_);
    gemm_tc<false><<<gpw, 256, GT_SMEM>>>(p_wcvt, p_norm, p_t,
                                 img_pw_b, wm_pw_b, (size_t)C3_ * C_, B_,
                                 C3_, HW_, C_, (size_t)C_ * HW_, (size_t)C3_ * HW_);

    // 3) Grouped 3x3 conv
    dwconv_kernel<<<32 * 256, 256>>>(img_dw_w, img_dw_b, wm_dw_w, wm_dw_b);

    // 4) Cross-attention
    attn_tc_kernel<<<B_ * NH_ * 2, 256, SMEM_ATTN>>>();

    // 5) Final projection GEMM (kTile=32)
    dim3 gf(HW_ / 128, C_ / 128, B_);
    gemm_tc<true><<<gf, 256, GT_SMEM>>>(p_wcvt + (size_t)2 * C3_ * C_, p_attn, out,
                               nullptr, nullptr, 0, 1 << 30,
                               C_, HW_, 2 * C_, (size_t)2 * C_ * HW_, (size_t)C_ * HW_);
}

// round 16
// speedup vs baseline: 1.0036x; 1.0036x over previous
#include <cuda_runtime.h>
#include <math.h>

#define B_  16
#define C_  512
#define HW_ 1024
#define C3_ 1536
#define NH_ 8
#define HC_ 64

static __device__ float g_norm[(size_t)2 * B_ * C_ * HW_];
static __device__ float g_t   [(size_t)2 * B_ * C3_ * HW_];
static __device__ float g_qkv [(size_t)2 * B_ * C3_ * HW_];
static __device__ float g_attn[(size_t)B_ * 2 * C_ * HW_];
static __device__ float g_stats[2 * B_ * 2];
static __device__ float g_part[2 * B_ * 16 * 2];
static __device__ float g_wcvt[2 * C3_ * C_ + 2 * C_ * C_];

// ---------------------------------------------------------------------------
// tf32 helpers
// ---------------------------------------------------------------------------
__device__ __forceinline__ unsigned f2tf32(float f) {
    unsigned r; asm("cvt.rna.tf32.f32 %0, %1;" : "=r"(r) : "f"(f)); return r;
}
__device__ __forceinline__ float tf32r(float f) {
    return __uint_as_float(f2tf32(f));
}
__device__ __forceinline__ void mma_tf32(float* c, const unsigned* a, const unsigned* b) {
    asm volatile(
        "mma.sync.aligned.m16n8k8.row.col.f32.tf32.tf32.f32 "
        "{%0,%1,%2,%3}, {%4,%5,%6,%7}, {%8,%9}, {%0,%1,%2,%3};"
        : "+f"(c[0]), "+f"(c[1]), "+f"(c[2]), "+f"(c[3])
        : "r"(a[0]), "r"(a[1]), "r"(a[2]), "r"(a[3]), "r"(b[0]), "r"(b[1]));
}
__device__ __forceinline__ void mma_u(float* c, unsigned a0, unsigned a1, unsigned a2,
                                      unsigned a3, unsigned b0, unsigned b1) {
    asm volatile(
        "mma.sync.aligned.m16n8k8.row.col.f32.tf32.tf32.f32 "
        "{%0,%1,%2,%3}, {%4,%5,%6,%7}, {%8,%9}, {%0,%1,%2,%3};"
        : "+f"(c[0]), "+f"(c[1]), "+f"(c[2]), "+f"(c[3])
        : "r"(a0), "r"(a1), "r"(a2), "r"(a3), "r"(b0), "r"(b1));
}

struct alignas(8) u2 { unsigned hi, lo; };

__device__ __forceinline__ u2 split_tf32(float x) {
    u2 r;
    asm("cvt.rna.tf32.f32 %0, %1;" : "=r"(r.hi) : "f"(x));
    float d = x - __uint_as_float(r.hi);
    asm("cvt.rna.tf32.f32 %0, %1;" : "=r"(r.lo) : "f"(d));
    return r;
}

__device__ __forceinline__ void cp16(void* sdst, const void* gsrc) {
    unsigned s = (unsigned)__cvta_generic_to_shared(sdst);
    asm volatile("cp.async.cg.shared.global [%0], [%1], 16;" :: "r"(s), "l"(gsrc));
}

// ---------------------------------------------------------------------------
// Kernel 0: pre-round GEMM weights to tf32 values
// ---------------------------------------------------------------------------
__global__ __launch_bounds__(256)
void cvt_weights(const float* __restrict__ wa, const float* __restrict__ wb,
                 const float* __restrict__ wp) {
    int idx = blockIdx.x * 256 + threadIdx.x;
    const int NA = C3_ * C_ / 4, NP = 2 * C_ * C_ / 4;
    float4 v;
    float4* dst = (float4*)g_wcvt;
    if (idx < NA)               v = ((const float4*)wa)[idx];
    else if (idx < 2 * NA)      v = ((const float4*)wb)[idx - NA];
    else if (idx < 2 * NA + NP) v = ((const float4*)wp)[idx - 2 * NA];
    else return;
    v.x = tf32r(v.x); v.y = tf32r(v.y); v.z = tf32r(v.z); v.w = tf32r(v.w);
    dst[idx] = v;
}

// ---------------------------------------------------------------------------
// Kernel 1a/1b: two-stage LayerNorm statistics
// ---------------------------------------------------------------------------
__global__ __launch_bounds__(256)
void ln_stats_part(const float* __restrict__ img, const float* __restrict__ wm) {
    int blk = blockIdx.x;
    int seg = blk & 15, sb = blk >> 4;
    int s = sb >> 4, b = sb & 15;
    const int SEG4 = C_ * HW_ / 4 / 16;
    const float4* x = (const float4*)((s ? wm : img) + (size_t)b * C_ * HW_)
                      + (size_t)seg * SEG4;
    float sum = 0.f, sq = 0.f;
    for (int i = threadIdx.x; i < SEG4; i += 256) {
        float4 v = x[i];
        sum += v.x + v.y + v.z + v.w;
        sq  += v.x * v.x + v.y * v.y + v.z * v.z + v.w * v.w;
    }
    __shared__ float s1[256], s2[256];
    s1[threadIdx.x] = sum; s2[threadIdx.x] = sq;
    __syncthreads();
    for (int st = 128; st > 0; st >>= 1) {
        if (threadIdx.x < st) {
            s1[threadIdx.x] += s1[threadIdx.x + st];
            s2[threadIdx.x] += s2[threadIdx.x + st];
        }
        __syncthreads();
    }
    if (threadIdx.x == 0) {
        g_part[blk * 2 + 0] = s1[0];
        g_part[blk * 2 + 1] = s2[0];
    }
}

__global__ void ln_stats_final() {
    int t = threadIdx.x;
    if (t >= 32) return;
    float sum = 0.f, sq = 0.f;
#pragma unroll
    for (int i = 0; i < 16; i++) {
        sum += g_part[(t * 16 + i) * 2 + 0];
        sq  += g_part[(t * 16 + i) * 2 + 1];
    }
    float inv_n = 1.f / (float)(C_ * HW_);
    float mu  = sum * inv_n;
    float var = sq * inv_n - mu * mu;
    g_stats[t * 2 + 0] = mu;
    g_stats[t * 2 + 1] = rsqrtf(var + 1e-5f);
}

// ---------------------------------------------------------------------------
// Kernel 2: apply LN affine, output tf32-rounded
// ---------------------------------------------------------------------------
__global__ __launch_bounds__(256)
void ln_apply(const float* __restrict__ img, const float* __restrict__ wm,
              const float* __restrict__ iw, const float* __restrict__ ib,
              const float* __restrict__ ww, const float* __restrict__ wb) {
    const int Q = C_ * HW_ / 4;
    size_t idx = (size_t)blockIdx.x * 256 + threadIdx.x;
    const size_t half = (size_t)B_ * Q;
    if (idx >= 2 * half) return;
    int s = idx >= half;
    size_t r = idx - (size_t)s * half;
    int b = (int)(r / Q);
    int chw = (int)(r % Q);
    const float4* x  = (const float4*)(s ? wm : img) + (size_t)b * Q;
    const float4* w  = (const float4*)(s ? ww : iw);
    const float4* bb = (const float4*)(s ? wb : ib);
    float mu   = g_stats[(s * 16 + b) * 2 + 0];
    float rstd = g_stats[(s * 16 + b) * 2 + 1];
    float4 xv = x[chw], wv = w[chw], bv = bb[chw];
    float4 o;
    o.x = tf32r((xv.x - mu) * rstd * wv.x + bv.x);
    o.y = tf32r((xv.y - mu) * rstd * wv.y + bv.y);
    o.z = tf32r((xv.z - mu) * rstd * wv.z + bv.z);
    o.w = tf32r((xv.w - mu) * rstd * wv.w + bv.w);
    ((float4*)g_norm)[idx] = o;
}

// ---------------------------------------------------------------------------
// Kernel 3/6: tf32 TC GEMM, cp.async double-buffered, pre-rounded operands.
//   zHalf: blocks with blockIdx.z >= zHalf use A+strideA and bias2.
// ---------------------------------------------------------------------------
template <bool TA>
__global__ __launch_bounds__(256)
void gemm_tc(const float* __restrict__ A, const float* __restrict__ Bm,
             float* __restrict__ Cm, const float* __restrict__ bias,
             const float* __restrict__ bias2, size_t strideA, int zHalf,
             int M, int N, int K, size_t strideB, size_t strideC) {
    __shared__ float As[2][2560];
    __shared__ float Bs[2][16 * 132];
    if ((int)blockIdx.z >= zHalf) {
        A += strideA;
        bias = bias2;
    }
    const float* Bb = Bm + (size_t)blockIdx.z * strideB;
    float* Cb = Cm + (size_t)blockIdx.z * strideC;
    int m0 = blockIdx.y * 128, n0 = blockIdx.x * 128;
    int tid = threadIdx.x, lane = tid & 31, wid = tid >> 5;
    int warpM = wid & 3, warpN = wid >> 2;
    int gi = lane >> 2, li = lane & 3;

    float acc[2][8][4];
#pragma unroll
    for (int mi = 0; mi < 2; mi++)
#pragma unroll
        for (int ni = 0; ni < 8; ni++)
#pragma unroll
            for (int j = 0; j < 4; j++) acc[mi][ni][j] = 0.f;

    const int T = K / 16;

#define COPY_TILE(t, buf)                                                        \
    {                                                                            \
        int k0c = (t) * 16;                                                      \
        _Pragma("unroll")                                                        \
        for (int r = 0; r < 2; r++) {                                            \
            int idx = tid + r * 256;                                             \
            if (TA) {                                                            \
                int kl = idx >> 5, mq = idx & 31;                                \
                cp16(&As[buf][kl * 132 + mq * 4],                                \
                     &A[(size_t)(k0c + kl) * M + m0 + mq * 4]);                  \
            } else {                                                             \
                int ml = idx >> 2, kq = idx & 3;                                 \
                cp16(&As[buf][ml * 20 + kq * 4],                                 \
                     &A[(size_t)(m0 + ml) * K + k0c + kq * 4]);                  \
            }                                                                    \
            int kl = idx >> 5, nq = idx & 31;                                    \
            cp16(&Bs[buf][kl * 132 + nq * 4],                                    \
                 &Bb[(size_t)(k0c + kl) * N + n0 + nq * 4]);                     \
        }                                                                        \
        asm volatile("cp.async.commit_group;");                                  \
    }

    COPY_TILE(0, 0);

    for (int t = 0; t < T; t++) {
        int buf = t & 1;
        __syncthreads();
        if (t + 1 < T) {
            COPY_TILE(t + 1, buf ^ 1);
            asm volatile("cp.async.wait_group 1;");
        } else {
            asm volatile("cp.async.wait_group 0;");
        }
        __syncthreads();
#pragma unroll
        for (int ks = 0; ks < 2; ks++) {
            int k8 = ks * 8;
            unsigned ua[2][4];
#pragma unroll
            for (int mi = 0; mi < 2; mi++) {
                int m = warpM * 32 + mi * 16 + gi;
                if (TA) {
                    ua[mi][0] = __float_as_uint(As[buf][(k8 + li) * 132 + m]);
                    ua[mi][1] = __float_as_uint(As[buf][(k8 + li) * 132 + m + 8]);
                    ua[mi][2] = __float_as_uint(As[buf][(k8 + li + 4) * 132 + m]);
                    ua[mi][3] = __float_as_uint(As[buf][(k8 + li + 4) * 132 + m + 8]);
                } else {
                    ua[mi][0] = __float_as_uint(As[buf][m * 20 + k8 + li]);
                    ua[mi][1] = __float_as_uint(As[buf][(m + 8) * 20 + k8 + li]);
                    ua[mi][2] = __float_as_uint(As[buf][m * 20 + k8 + li + 4]);
                    ua[mi][3] = __float_as_uint(As[buf][(m + 8) * 20 + k8 + li + 4]);
                }
            }
            unsigned ub[8][2];
#pragma unroll
            for (int ni = 0; ni < 8; ni++) {
                int nn = warpN * 64 + ni * 8 + gi;
                ub[ni][0] = __float_as_uint(Bs[buf][(k8 + li) * 132 + nn]);
                ub[ni][1] = __float_as_uint(Bs[buf][(k8 + li + 4) * 132 + nn]);
            }
#pragma unroll
            for (int mi = 0; mi < 2; mi++)
#pragma unroll
                for (int ni = 0; ni < 8; ni++)
                    mma_tf32(acc[mi][ni], ua[mi], ub[ni]);
        }
    }

#pragma unroll
    for (int mi = 0; mi < 2; mi++) {
        int mrow = m0 + warpM * 32 + mi * 16 + gi;
        float bv0 = bias ? bias[mrow] : 0.f;
        float bv1 = bias ? bias[mrow + 8] : 0.f;
#pragma unroll
        for (int ni = 0; ni < 8; ni++) {
            int n = n0 + warpN * 64 + ni * 8 + 2 * li;
            float2 v0 = {acc[mi][ni][0] + bv0, acc[mi][ni][1] + bv0};
            float2 v1 = {acc[mi][ni][2] + bv1, acc[mi][ni][3] + bv1};
            *(float2*)&Cb[(size_t)mrow * N + n] = v0;
            *(float2*)&Cb[(size_t)(mrow + 8) * N + n] = v1;
        }
    }
}

// ---------------------------------------------------------------------------
// Kernel 4: grouped 3x3 conv, register-blocked
// ---------------------------------------------------------------------------
__global__ __launch_bounds__(256)
void dwconv_kernel(const float* __restrict__ wimg, const float* __restrict__ bimg,
                   const float* __restrict__ wwm,  const float* __restrict__ bwm) {
    __shared__ float sin_[6 * HW_];
    __shared__ float sw[162];
    __shared__ float sbias[6];
    int blk = blockIdx.x;
    int gp = blk & 255, sb = blk >> 8;
    int s = sb >> 4;
    int tid = threadIdx.x;
    int c0 = gp * 6;
    const float* in = g_t + ((size_t)sb * C3_ + c0) * HW_;
#pragma unroll
    for (int r = 0; r < 6; r++) {
        int idx = tid + r * 256;
        ((float4*)sin_)[idx] = ((const float4*)in)[idx];
    }
    const float* w = (s ? wwm : wimg) + (size_t)c0 * 27;
    if (tid < 162) sw[tid] = w[tid];
    if (tid < 6) sbias[tid] = (s ? bwm : bimg)[c0 + tid];
    __syncthreads();
    float* outp = g_qkv + ((size_t)sb * C3_ + c0) * HW_;
#pragma unroll
    for (int task = 0; task < 3; task++) {
        int t = task * 256 + tid;
        int o = t >> 7;
        int rest = t & 127;
        int y = rest >> 2;
        int seg = rest & 3;
        int x0 = seg * 8;
        float acc[8];
        float bv = sbias[o];
#pragma unroll
        for (int j = 0; j < 8; j++) acc[j] = bv;
        const float* wo = &sw[o * 27];
        const float* chan = &sin_[(o >= 3 ? 3 : 0) * HW_];
#pragma unroll
        for (int i = 0; i < 3; i++) {
            const float* cb = chan + i * HW_;
            const float* wi = wo + i * 9;
#pragma unroll
            for (int ky = 0; ky < 3; ky++) {
                int yy = y + ky - 1;
                if (yy < 0 || yy >= 32) continue;
                const float* rr = cb + yy * 32;
                float v[10];
                v[0] = (x0 > 0) ? rr[x0 - 1] : 0.f;
                float4 a4 = *(const float4*)&rr[x0];
                float4 b4 = *(const float4*)&rr[x0 + 4];
                v[1] = a4.x; v[2] = a4.y; v[3] = a4.z; v[4] = a4.w;
                v[5] = b4.x; v[6] = b4.y; v[7] = b4.z; v[8] = b4.w;
                v[9] = (x0 + 8 < 32) ? rr[x0 + 8] : 0.f;
                float w0 = wi[ky * 3 + 0], w1 = wi[ky * 3 + 1], w2 = wi[ky * 3 + 2];
#pragma unroll
                for (int j = 0; j < 8; j++)
                    acc[j] += w0 * v[j] + w1 * v[j + 1] + w2 * v[j + 2];
            }
        }
        float4 o0 = {acc[0], acc[1], acc[2], acc[3]};
        float4 o1 = {acc[4], acc[5], acc[6], acc[7]};
        *(float4*)&outp[(size_t)o * HW_ + y * 32 + x0] = o0;
        *(float4*)&outp[(size_t)o * HW_ + y * 32 + x0 + 4] = o1;
    }
}

// ---------------------------------------------------------------------------
// Kernel 5: TC cross-attention. Phase 1 = tf32x3 (full precision logits);
//   Phase 3 = tf32x2 (S_hi*V_hi + S_hi*V_lo) — S rounded to tf32, V exact.
// ---------------------------------------------------------------------------
#define KS_STRIDE 35
#define QS_STRIDE 67
#define S_STRIDE  68
#define SMEM_KS_BYTES  (128 * KS_STRIDE * 8)
#define SMEM_QS_BYTES  (32 * QS_STRIDE * 8)
#define SMEM_S_OFF     (SMEM_KS_BYTES + SMEM_QS_BYTES)
#define SMEM_ATTN      (SMEM_S_OFF + 128 * S_STRIDE * 4)

__global__ __launch_bounds__(256)
void attn_tc_kernel() {
    extern __shared__ char smem_raw[];
    u2*    Ks = (u2*)smem_raw;
    u2*    Qs = (u2*)(smem_raw + SMEM_KS_BYTES);
    float* S  = (float*)(smem_raw + SMEM_S_OFF);

    int bid = blockIdx.x;
    int s = bid & 1, n = (bid >> 1) & 7, b = bid >> 4;
    int tid = threadIdx.x, lane = tid & 31, w = tid >> 5;
    int gi = lane >> 2, li = lane & 3;

    const size_t SB = (size_t)B_ * C3_ * HW_;
    const float* qbase  = g_qkv + (s ? SB : 0) + ((size_t)b * C3_ + n * HC_) * HW_;
    const float* k0base = g_qkv + ((size_t)b * C3_ + C_ + n * HC_) * HW_;
    const float* k1base = k0base + SB;
    const float* v0base = g_qkv + ((size_t)b * C3_ + 2 * C_ + n * HC_) * HW_;
    const float* v1base = v0base + SB;

    int r8 = tid >> 3;
    int q4 = (tid & 7) * 4;
    const float* kp[4];
    u2* kdst[4];
#pragma unroll
    for (int i = 0; i < 4; i++) {
        int kr = r8 + 32 * i;
        kp[i] = ((kr < 64) ? k0base + (size_t)kr * HW_
                           : k1base + (size_t)(kr - 64) * HW_) + q4;
        kdst[i] = &Ks[kr * KS_STRIDE + q4];
    }
    const float* qp[2];
#pragma unroll
    for (int i = 0; i < 2; i++)
        qp[i] = qbase + (size_t)(r8 + 32 * i) * HW_ + q4;
    const float* vp[4];
#pragma unroll
    for (int i = 0; i < 4; i++) {
        int kr = r8 + 32 * i;
        vp[i] = ((kr < 64) ? v0base + (size_t)kr * HW_
                           : v1base + (size_t)(kr - 64) * HW_) + q4;
    }

    // ======== Phase 1: S = K . Q^T (tf32x3, warp tile 32k x 32q) ========
    int wM = w & 3, wN = w >> 2;
    float accS[2][4][4];
#pragma unroll
    for (int mi = 0; mi < 2; mi++)
#pragma unroll
        for (int ni = 0; ni < 4; ni++)
#pragma unroll
            for (int j = 0; j < 4; j++) accS[mi][ni][j] = 0.f;

    float4 kreg[4], qreg[2];
#pragma unroll
    for (int i = 0; i < 4; i++) kreg[i] = *(const float4*)kp[i];
#pragma unroll
    for (int i = 0; i < 2; i++) qreg[i] = *(const float4*)qp[i];

    for (int pc = 0; pc < 32; pc++) {
        __syncthreads();
#pragma unroll
        for (int i = 0; i < 4; i++) {
            kdst[i][0] = split_tf32(kreg[i].x); kdst[i][1] = split_tf32(kreg[i].y);
            kdst[i][2] = split_tf32(kreg[i].z); kdst[i][3] = split_tf32(kreg[i].w);
        }
#pragma unroll
        for (int i = 0; i < 2; i++) {
            int qr = r8 + 32 * i;
            Qs[(q4 + 0) * QS_STRIDE + qr] = split_tf32(qreg[i].x);
            Qs[(q4 + 1) * QS_STRIDE + qr] = split_tf32(qreg[i].y);
            Qs[(q4 + 2) * QS_STRIDE + qr] = split_tf32(qreg[i].z);
            Qs[(q4 + 3) * QS_STRIDE + qr] = split_tf32(qreg[i].w);
        }
        __syncthreads();
        if (pc < 31) {
            int off = (pc + 1) * 32;
#pragma unroll
            for (int i = 0; i < 4; i++) kreg[i] = *(const float4*)(kp[i] + off);
#pragma unroll
            for (int i = 0; i < 2; i++) qreg[i] = *(const float4*)(qp[i] + off);
        }
#pragma unroll
        for (int ks = 0; ks < 4; ks++) {
            int k8 = ks * 8;
            u2 a[2][4], bq[4][2];
#pragma unroll
            for (int mi = 0; mi < 2; mi++) {
                int m = wM * 32 + mi * 16 + gi;
                a[mi][0] = Ks[m * KS_STRIDE + k8 + li];
                a[mi][1] = Ks[(m + 8) * KS_STRIDE + k8 + li];
                a[mi][2] = Ks[m * KS_STRIDE + k8 + li + 4];
                a[mi][3] = Ks[(m + 8) * KS_STRIDE + k8 + li + 4];
            }
#pragma unroll
            for (int ni = 0; ni < 4; ni++) {
                int q = wN * 32 + ni * 8 + gi;
                bq[ni][0] = Qs[(k8 + li) * QS_STRIDE + q];
                bq[ni][1] = Qs[(k8 + li + 4) * QS_STRIDE + q];
            }
#pragma unroll
            for (int mi = 0; mi < 2; mi++)
#pragma unroll
                for (int ni = 0; ni < 4; ni++) {
                    float* c = accS[mi][ni];
                    mma_u(c, a[mi][0].hi, a[mi][1].hi, a[mi][2].hi, a[mi][3].hi,
                          bq[ni][0].hi, bq[ni][1].hi);
                    mma_u(c, a[mi][0].hi, a[mi][1].hi, a[mi][2].hi, a[mi][3].hi,
                          bq[ni][0].lo, bq[ni][1].lo);
                    mma_u(c, a[mi][0].lo, a[mi][1].lo, a[mi][2].lo, a[mi][3].lo,
                          bq[ni][0].hi, bq[ni][1].hi);
                }
        }
    }
#pragma unroll
    for (int mi = 0; mi < 2; mi++)
#pragma unroll
        for (int ni = 0; ni < 4; ni++) {
            int m = wM * 32 + mi * 16 + gi;
            int q = wN * 32 + ni * 8 + 2 * li;
            float2 v0 = {accS[mi][ni][0], accS[mi][ni][1]};
            float2 v1 = {accS[mi][ni][2], accS[mi][ni][3]};
            *(float2*)&S[m * S_STRIDE + q] = v0;
            *(float2*)&S[(m + 8) * S_STRIDE + q] = v1;
        }
    __syncthreads();

    // ======== Phase 2: softmax over q per k-row ========
    if (tid < 128) {
        float* row = &S[tid * S_STRIDE];
        float mx = -1e30f;
#pragma unroll 8
        for (int j = 0; j < 64; j++) mx = fmaxf(mx, row[j]);
        float sum = 0.f;
#pragma unroll 8
        for (int j = 0; j < 64; j++) {
            float e = __expf(row[j] - mx);
            row[j] = e; sum += e;
        }
        float inv = 1.f / sum;
#pragma unroll 8
        for (int j = 0; j < 64; j++) row[j] *= inv;
    }

    // ======== Phase 3: out = S^T . V (tf32x2: S_hi*(V_hi+V_lo)) ========
    int wM3 = w & 3, wN3 = w >> 2;
    float* outbase = g_attn + ((size_t)b * (2 * C_) + n * 128 + s * 64) * HW_;
    float4 vreg[4];
#pragma unroll
    for (int i = 0; i < 4; i++) vreg[i] = *(const float4*)vp[i];

    for (int pc = 0; pc < 32; pc++) {
        int p0 = pc * 32;
        __syncthreads();
#pragma unroll
        for (int i = 0; i < 4; i++) {
            kdst[i][0] = split_tf32(vreg[i].x); kdst[i][1] = split_tf32(vreg[i].y);
            kdst[i][2] = split_tf32(vreg[i].z); kdst[i][3] = split_tf32(vreg[i].w);
        }
        __syncthreads();
        if (pc < 31) {
            int off = (pc + 1) * 32;
#pragma unroll
            for (int i = 0; i < 4; i++) vreg[i] = *(const float4*)(vp[i] + off);
        }
        float acc3[2][4];
#pragma unroll
        for (int ni = 0; ni < 2; ni++)
#pragma unroll
            for (int j = 0; j < 4; j++) acc3[ni][j] = 0.f;
#pragma unroll
        for (int ks = 0; ks < 16; ks++) {
            int k8 = ks * 8;
            int m = wM3 * 16 + gi;
            unsigned a0 = f2tf32(S[(k8 + li) * S_STRIDE + m]);
            unsigned a1 = f2tf32(S[(k8 + li) * S_STRIDE + m + 8]);
            unsigned a2 = f2tf32(S[(k8 + li + 4) * S_STRIDE + m]);
            unsigned a3 = f2tf32(S[(k8 + li + 4) * S_STRIDE + m + 8]);
            u2 bv[2][2];
#pragma unroll
            for (int ni = 0; ni < 2; ni++) {
                int p = wN3 * 16 + ni * 8 + gi;
                bv[ni][0] = Ks[(k8 + li) * KS_STRIDE + p];
                bv[ni][1] = Ks[(k8 + li + 4) * KS_STRIDE + p];
            }
#pragma unroll
            for (int ni = 0; ni < 2; ni++) {
                float* c = acc3[ni];
                mma_u(c, a0, a1, a2, a3, bv[ni][0].hi, bv[ni][1].hi);
                mma_u(c, a0, a1, a2, a3, bv[ni][0].lo, bv[ni][1].lo);
            }
        }
        int qrow = wM3 * 16 + gi;
#pragma unroll
        for (int ni = 0; ni < 2; ni++) {
            int p = p0 + wN3 * 16 + ni * 8 + 2 * li;
            float2 v0 = {tf32r(acc3[ni][0]), tf32r(acc3[ni][1])};
            float2 v1 = {tf32r(acc3[ni][2]), tf32r(acc3[ni][3])};
            *(float2*)&outbase[(size_t)qrow * HW_ + p] = v0;
            *(float2*)&outbase[(size_t)(qrow + 8) * HW_ + p] = v1;
        }
    }
}

// ---------------------------------------------------------------------------
extern "C" void kernel_launch(void* const* d_in, const int* in_sizes, int n_in,
                              void* d_out, int out_size) {
    const float* image     = (const float*)d_in[0];
    const float* watermark = (const float*)d_in[1];
    const float* img_ln_w  = (const float*)d_in[2];
    const float* img_ln_b  = (const float*)d_in[3];
    const float* wm_ln_w   = (const float*)d_in[4];
    const float* wm_ln_b   = (const float*)d_in[5];
    const float* img_pw_w  = (const float*)d_in[6];
    const float* img_pw_b  = (const float*)d_in[7];
    const float* img_dw_w  = (const float*)d_in[8];
    const float* img_dw_b  = (const float*)d_in[9];
    const float* wm_pw_w   = (const float*)d_in[10];
    const float* wm_pw_b   = (const float*)d_in[11];
    const float* wm_dw_w   = (const float*)d_in[12];
    const float* wm_dw_b   = (const float*)d_in[13];
    const float* proj      = (const float*)d_in[14];
    float* out = (float*)d_out;

    float *p_norm, *p_t, *p_attn, *p_wcvt;
    cudaGetSymbolAddress((void**)&p_norm, g_norm);
    cudaGetSymbolAddress((void**)&p_t,    g_t);
    cudaGetSymbolAddress((void**)&p_attn, g_attn);
    cudaGetSymbolAddress((void**)&p_wcvt, g_wcvt);

    cudaFuncSetAttribute(attn_tc_kernel,
                         cudaFuncAttributeMaxDynamicSharedMemorySize, SMEM_ATTN);

    // 0) pre-round GEMM weights
    int cvt4 = (2 * C3_ * C_ + 2 * C_ * C_) / 4;
    cvt_weights<<<(cvt4 + 255) / 256, 256>>>(img_pw_w, wm_pw_w, proj);

    // 1) LayerNorm (two-stage stats)
    ln_stats_part<<<512, 256>>>(image, watermark);
    ln_stats_final<<<1, 32>>>();
    size_t total4 = (size_t)2 * B_ * C_ * HW_ / 4;
    ln_apply<<<(unsigned)((total4 + 255) / 256), 256>>>(
        image, watermark, img_ln_w, img_ln_b, wm_ln_w, wm_ln_b);

    // 2) Pointwise 1x1 conv — both streams in one launch
    dim3 gpw(HW_ / 128, C3_ / 128, 2 * B_);
    gemm_tc<false><<<gpw, 256>>>(p_wcvt, p_norm, p_t,
                                 img_pw_b, wm_pw_b, (size_t)C3_ * C_, B_,
                                 C3_, HW_, C_, (size_t)C_ * HW_, (size_t)C3_ * HW_);

    // 3) Grouped 3x3 conv
    dwconv_kernel<<<32 * 256, 256>>>(img_dw_w, img_dw_b, wm_dw_w, wm_dw_b);

    // 4) Cross-attention
    attn_tc_kernel<<<B_ * NH_ * 2, 256, SMEM_ATTN>>>();

    // 5) Final projection GEMM
    dim3 gf(HW_ / 128, C_ / 128, B_);
    gemm_tc<true><<<gf, 256>>>(p_wcvt + (size_t)2 * C3_ * C_, p_attn, out,
                               nullptr, nullptr, 0, 1 << 30,
                               C_, HW_, 2 * C_, (size_t)2 * C_ * HW_, (size_t)C_ * HW_);
}